// round 9
// baseline (speedup 1.0000x reference)
#include <cuda_runtime.h>

#define BB 4
#define NN 2048
#define MM 2049
#define GG 1024
#define CC 3
#define MMQ (MM*MM)                 // 4198401

typedef unsigned long long u64;

// ---------------- scratch (device globals, zero-initialized at load) --------
// Cleaning schedule (race-free across graph replays):
//   g_bestg/g_nmax : written K1, read tail phase1, cleaned tail phase2
//   g_cnt/g_keep   : written tail ph2, read ph3, cleaned by NEXT replay's K1
//   g_bar0/g_bar1/g_ticket : used by tail, cleaned by NEXT replay's K1
//   g_cd/g_sem/g_mf/g_mb : atomic-acc, cleaned in tail finalize
//   g_nearest/g_nextg : fully overwritten every replay
__device__ u64   g_bestg[BB*GG];    // ~((distbits<<32)|pred); 0 = unassigned
__device__ int   g_nmax[BB];
__device__ int   g_nearest[BB*NN];
__device__ int   g_nextg[BB*GG];
__device__ int   g_cnt[BB*NN];
__device__ u64   g_keep[BB*NN];     // ~((distbits<<32)|row); 0 = empty
__device__ float g_cd[BB], g_sem[BB];
__device__ float g_mf[BB], g_mb[BB];
__device__ unsigned g_bar0, g_bar1, g_ticket;

// pos = position * 0.15 + bias, NO fma contraction (match XLA's separate ops)
__device__ __forceinline__ float posx_of(float p){ return __fadd_rn(__fmul_rn(p,0.15f), -29.925f); }
__device__ __forceinline__ float posy_of(float p){ return __fadd_rn(__fmul_rn(p,0.15f), -14.925f); }

__device__ __forceinline__ float pdist(float ax,float ay,float bx,float by){
    float dx = __fsub_rn(ax,bx), dy = __fsub_rn(ay,by);
    float d2 = __fadd_rn(__fmul_rn(dx,dx), __fmul_rn(dy,dy));
    return sqrtf(d2);
}

// ===== K1: [blocks 0..1023] nearest-gt (warp/pred)  ++
//           [blocks 1024..5124] zero-fill A region + clean scratch ==========
#define NBLK 1024                       // BB*NN/8 nearest blocks
#define ZVEC 4198401                    // float4 count of zero region
#define ZBLK 4101                       // ceil(ZVEC/1024)

__global__ void __launch_bounds__(256) k1_zero_nearest(
                           const float* __restrict__ positions,
                           const float* __restrict__ gt_pts,
                           const int*   __restrict__ gt_type,
                           const float* __restrict__ semantics,
                           float* __restrict__ out,
                           float* __restrict__ sg_out)
{
    if (blockIdx.x >= NBLK) {           // ---------- zero blocks ------------
        unsigned zb = blockIdx.x - NBLK;
        float4* vout = (float4*)out;
        #pragma unroll
        for (int k = 0; k < 4; ++k) {
            unsigned v = zb*1024u + k*256u + threadIdx.x;
            if (v < ZVEC) vout[v] = make_float4(0.f,0.f,0.f,0.f);
        }
        if (zb < 32) {                  // clean cnt/keep for this replay
            int idx = zb*256 + threadIdx.x;      // covers BB*NN = 8192
            g_cnt[idx] = 0;
            g_keep[idx] = 0ULL;
        }
        if (zb == 32 && threadIdx.x == 0) {
            g_bar0 = 0u; g_bar1 = 0u; g_ticket = 0u;
        }
        if (zb == 0 && threadIdx.x == 0) {
            out[16793604] = 0.f; out[16793605] = 0.f; out[16793606] = 0.f;
        }
        return;
    }

    // ---------------- nearest blocks (scheduled first) ---------------------
    __shared__ float s_cd, s_sem;
    __shared__ int   s_nm;
    __shared__ int   s_cls[8];

    int tid  = threadIdx.x;
    int wid  = tid >> 5;
    int lane = tid & 31;
    int pred = blockIdx.x*8 + wid;      // global pred id, 0..BB*NN-1
    int b    = pred >> 11;
    int pi   = pred & (NN-1);

    if (tid == 0) { s_cd = 0.f; s_sem = 0.f; s_nm = 0; }

    float2 praw = ((const float2*)positions)[pred];
    float px = posx_of(praw.x), py = posy_of(praw.y);

    const float4* gp4 = (const float4*)(gt_pts + (size_t)b*GG*2);  // 512 float4

    // exact argmin of sqrt(d2): d2-pruning + lazy sqrt; preserves jnp.argmin
    // first-index tie rule (sqrt monotone; ascending-g visit; strict <).
    float bestd2 = 3.4e38f, bests = 3.4e38f; int bestg = 0;
    #pragma unroll
    for (int k = 0; k < 16; ++k) {
        float4 f = gp4[k*32 + lane];    // points g0 = 2*(k*32+lane), g0+1
        int g0 = 2*(k*32 + lane);
        {
            float dx = __fsub_rn(px, f.x), dy = __fsub_rn(py, f.y);
            float d2 = __fadd_rn(__fmul_rn(dx,dx), __fmul_rn(dy,dy));
            if (d2 < bestd2) {
                bestd2 = d2;
                float s = sqrtf(d2);
                if (s < bests) { bests = s; bestg = g0; }
            }
        }
        {
            float dx = __fsub_rn(px, f.z), dy = __fsub_rn(py, f.w);
            float d2 = __fadd_rn(__fmul_rn(dx,dx), __fmul_rn(dy,dy));
            if (d2 < bestd2) {
                bestd2 = d2;
                float s = sqrtf(d2);
                if (s < bests) { bests = s; bestg = g0 + 1; }
            }
        }
    }
    u64 key = ((u64)__float_as_uint(bests) << 32) | (unsigned)bestg;
    #pragma unroll
    for (int o = 16; o; o >>= 1) {
        u64 other = __shfl_xor_sync(0xffffffffu, key, o);
        if (other < key) key = other;   // tie -> smaller g (low bits)
    }
    __syncthreads();                    // s_cd/s_sem/s_nm initialized

    if (lane == 0) {
        int gb  = (int)(key & 0xffffffffULL);
        float d = __uint_as_float((unsigned)(key >> 32));
        g_nearest[pred] = gb;
        atomicMax(&s_nm, gb);
        atomicAdd(&s_cd, d);
        u64 pk = ((u64)__float_as_uint(d) << 32) | (unsigned)pi;
        atomicMax(&g_bestg[b*GG + gb], ~pk);          // min(key) == max(~key)
        int cls = gt_type[b*GG + gb];
        s_cls[wid] = cls;
        atomicAdd(&s_sem, semantics[(size_t)b*CC*NN + (size_t)cls*NN + pi]);
    }
    __syncthreads();

    if (tid < 24) {                     // sg: 3 classes x 8 consecutive preds
        int c = tid >> 3, k = tid & 7;
        int p0 = (blockIdx.x & 255)*8;  // pred-in-batch base for this block
        sg_out[(size_t)b*CC*NN + (size_t)c*NN + p0 + k] = (s_cls[k]==c) ? 1.f : 0.f;
    }
    if (tid == 0) {
        atomicAdd(&g_cd[b], s_cd);
        atomicAdd(&g_sem[b], s_sem);
        atomicMax(&g_nmax[b], s_nm);
    }
}

// ---------------- software grid barrier (32 co-resident blocks) ------------
__device__ __forceinline__ void grid_barrier(unsigned* ctr)
{
    __syncthreads();
    if (threadIdx.x == 0) {
        __threadfence();                     // release prior writes
        atomicAdd(ctr, 1u);
        volatile unsigned* vc = ctr;
        while (*vc < 32u) { }
    }
    __syncthreads();
}

// ===== K2: fused tail — walk | barrier | count/keep | barrier | scatter ====
__global__ void __launch_bounds__(256) k2_fused(const int* __restrict__ gt_ins,
                                                const float* __restrict__ positions,
                                                const float* __restrict__ matches,
                                                float* __restrict__ out)
{
    int tid = threadIdx.x;
    int blk = blockIdx.x;                    // 32 blocks

    // ---- phase 1: walk once per g (blocks 0..15; 4/batch, smem-staged) ----
    if (blk < 16) {
        __shared__ int s_ins[GG];
        __shared__ int s_bp[GG];             // best pred + 1, 0 = none
        int b  = blk >> 2;
        int g0 = (blk & 3) * 256;
        for (int g = tid; g < GG; g += 256) {
            s_ins[g] = gt_ins[b*GG + g];
            u64 v = __ldcg(&g_bestg[b*GG + g]);
            s_bp[g] = v ? (int)((~v) & 0xffffffffULL) + 1 : 0;
        }
        __syncthreads();
        int nmaxb = __ldcg(&g_nmax[b]);

        int g = g0 + tid;
        int idx = g, steps = 0, res = -1;
        while (true) {                       // literal jax while_loop
            bool is_end = (idx >= nmaxb);
            int  gnr    = is_end ? -1 : (idx + 1);
            int  gn     = gnr & (GG-1);
            int  bp     = s_bp[gn];
            bool ex     = (!is_end) && (bp != 0);
            bool same   = (s_ins[idx & (GG-1)] == s_ins[gn]);
            bool matched= ex && same;
            res  = matched ? bp - 1 : -1;
            bool stop = matched || (!same) || (steps >= GG + 2);
            idx = gnr; steps++;
            if (stop) break;
        }
        g_nextg[b*GG + g] = res;
    }
    grid_barrier(&g_bar0);

    // ---- phase 2: per-pred counts + keep (global atomics) -----------------
    int t = blk*256 + tid;                   // 0..8191, one pred each
    int b = t >> 11, i = t & (NN-1);
    int res = __ldcg(&g_nextg[b*GG + g_nearest[t]]);
    float2 pi_raw = ((const float2*)positions)[t];
    if (res >= 0) {
        atomicAdd(&g_cnt[b*NN + res], 1);
        float2 pj = ((const float2*)positions)[b*NN + res];
        float d = pdist(posx_of(pi_raw.x), posy_of(pi_raw.y),
                        posx_of(pj.x),     posy_of(pj.y));
        u64 pk = ((u64)__float_as_uint(d) << 32) | (unsigned)i;
        atomicMax(&g_keep[b*NN + res], ~pk);
    }
    if (t < BB*GG) g_bestg[t] = 0ULL;        // self-clean (walk done)
    if (t < BB)    g_nmax[t]  = 0;
    grid_barrier(&g_bar1);

    // ---- phase 3: targets + scatter + loss gathers + finalize -------------
    int tf;
    if (res >= 0) {
        int cnt = __ldcg(&g_cnt[b*NN + res]);
        int keeprow = (int)((~__ldcg(&g_keep[b*NN + res])) & 0xffffffffULL);
        tf = (cnt <= 1 || keeprow == i) ? res : (MM-1);
    } else tf = MM-1;

    int cj = __ldcg(&g_cnt[t]);
    int tb = (cj == 0) ? (MM-1) : (int)((~__ldcg(&g_keep[t])) & 0xffffffffULL);

    size_t rowbase = (size_t)b*MMQ + (size_t)i*MM;
    out[3 + rowbase + tf] = 1.0f;            // row i's single 1
    if (tb == MM-1)                          // col i empty -> last row gets 1
        out[3 + (size_t)b*MMQ + (size_t)NN*MM + i] = 1.0f;

    float fv = matches[rowbase + tf];        // match[i, tgt_f[i]]
    float bv = matches[rowbase + tb];        // match[i, tgt_b[i]]
    #pragma unroll
    for (int o = 16; o; o >>= 1) {
        fv += __shfl_xor_sync(0xffffffffu, fv, o);
        bv += __shfl_xor_sync(0xffffffffu, bv, o);
    }
    if ((tid & 31) == 0) {                   // b warp-uniform
        atomicAdd(&g_mf[b], fv);
        atomicAdd(&g_mb[b], bv);
    }
    __syncthreads();

    if (tid == 0) {
        __threadfence();
        if (atomicAdd(&g_ticket, 1u) == 31u) {    // last block finalizes
            float cm = 0.f, ml = 0.f, sl = 0.f;
            const float invN = 1.0f / NN;
            #pragma unroll
            for (int bb = 0; bb < BB; ++bb) {
                cm += g_cd[bb] * invN;
                sl += -g_sem[bb] * invN;
                float lf = -g_mf[bb] * invN;
                float lb = -g_mb[bb] * invN;
                ml += 0.5f * (lf + lb);
                g_cd[bb]=0.f; g_sem[bb]=0.f; g_mf[bb]=0.f; g_mb[bb]=0.f;
            }
            const float invB = 1.0f / BB;
            out[0] = cm * invB;
            out[1] = ml * invB;
            out[2] = sl * invB;
        }
    }
}

extern "C" void kernel_launch(void* const* d_in, const int* in_sizes, int n_in,
                              void* d_out, int out_size)
{
    const float* matches   = (const float*)d_in[0];
    const float* positions = (const float*)d_in[1];
    const float* semantics = (const float*)d_in[2];
    /* d_in[3] masks: unused by reference */
    const float* gt_pts    = (const float*)d_in[4];
    const int*   gt_ins    = (const int*)d_in[5];
    const int*   gt_type   = (const int*)d_in[6];

    float* out = (float*)d_out;
    float* sg  = out + 3 + (size_t)BB*MMQ;

    k1_zero_nearest<<<NBLK + ZBLK, 256>>>(positions, gt_pts, gt_type,
                                          semantics, out, sg);
    k2_fused<<<32, 256>>>(gt_ins, positions, matches, out);
}

// round 10
// speedup vs baseline: 1.0893x; 1.0893x over previous
#include <cuda_runtime.h>

#define BB 4
#define NN 2048
#define MM 2049
#define GG 1024
#define CC 3
#define MMQ (MM*MM)                 // 4198401

typedef unsigned long long u64;

// ---------------- scratch (device globals, zero-initialized at load) --------
// Cleaning schedule (race-free across graph replays):
//   g_bestg/g_nmax : written K1 (atomicMax), read K2a, cleaned K2b
//   g_cnt/g_keep   : written K2b, read K3 (cross-thread), cleaned by NEXT
//                    replay's K1 zero-blocks (run before K2b)
//   g_cd/g_sem/g_mf/g_mb : atomic-acc, cleaned in K3 finalize
//   g_nearest/g_nextg/g_next : fully overwritten every replay
__device__ u64   g_bestg[BB*GG];    // ~((distbits<<32)|pred); 0 = unassigned
__device__ int   g_nmax[BB];
__device__ int   g_nearest[BB*NN];
__device__ int   g_nextg[BB*GG];
__device__ int   g_next[BB*NN];
__device__ int   g_cnt[BB*NN];
__device__ u64   g_keep[BB*NN];     // ~((distbits<<32)|row); 0 = empty
__device__ float g_cd[BB], g_sem[BB];
__device__ float g_mf[BB], g_mb[BB];
__device__ unsigned g_ticket;

// pos = position * 0.15 + bias, NO fma contraction (match XLA's separate ops)
__device__ __forceinline__ float posx_of(float p){ return __fadd_rn(__fmul_rn(p,0.15f), -29.925f); }
__device__ __forceinline__ float posy_of(float p){ return __fadd_rn(__fmul_rn(p,0.15f), -14.925f); }

__device__ __forceinline__ float pdist(float ax,float ay,float bx,float by){
    float dx = __fsub_rn(ax,bx), dy = __fsub_rn(ay,by);
    float d2 = __fadd_rn(__fmul_rn(dx,dx), __fmul_rn(dy,dy));
    return sqrtf(d2);
}

// ===== K1: [blocks 0..1023] nearest-gt (warp/pred)  ++
//           [blocks 1024..5124] zero-fill A region + clean cnt/keep =========
#define NBLK 1024                       // BB*NN/8 nearest blocks
#define ZVEC 4198401                    // float4 count of zero region
#define ZBLK 4101                       // ceil(ZVEC/1024)

__global__ void __launch_bounds__(256) k1_zero_nearest(
                           const float* __restrict__ positions,
                           const float* __restrict__ gt_pts,
                           const int*   __restrict__ gt_type,
                           const float* __restrict__ semantics,
                           float* __restrict__ out,
                           float* __restrict__ sg_out)
{
    if (blockIdx.x >= NBLK) {           // ---------- zero blocks ------------
        unsigned zb = blockIdx.x - NBLK;
        float4* vout = (float4*)out;
        #pragma unroll
        for (int k = 0; k < 4; ++k) {
            unsigned v = zb*1024u + k*256u + threadIdx.x;
            if (v < ZVEC) vout[v] = make_float4(0.f,0.f,0.f,0.f);
        }
        if (zb < 32) {                  // clean cnt/keep for this replay's K2b
            int idx = zb*256 + threadIdx.x;      // covers BB*NN = 8192
            g_cnt[idx] = 0;
            g_keep[idx] = 0ULL;
        }
        if (zb == 0 && threadIdx.x == 0) {
            out[16793604] = 0.f; out[16793605] = 0.f; out[16793606] = 0.f;
        }
        return;
    }

    // ---------------- nearest blocks (scheduled first) ---------------------
    __shared__ float s_cd, s_sem;
    __shared__ int   s_nm;
    __shared__ int   s_cls[8];

    int tid  = threadIdx.x;
    int wid  = tid >> 5;
    int lane = tid & 31;
    int pred = blockIdx.x*8 + wid;      // global pred id, 0..BB*NN-1
    int b    = pred >> 11;
    int pi   = pred & (NN-1);

    if (tid == 0) { s_cd = 0.f; s_sem = 0.f; s_nm = 0; }

    float2 praw = ((const float2*)positions)[pred];
    float px = posx_of(praw.x), py = posy_of(praw.y);

    const float4* gp4 = (const float4*)(gt_pts + (size_t)b*GG*2);  // 512 float4

    // Branchless argmin over d2 (no in-loop sqrt). sqrt monotone =>
    // argmin(d2) with strict < (ascending g) == first-index argmin(sqrt d2);
    // single sqrt after the reduction recovers the exact min distance.
    float bestd2 = 3.4e38f; int bestg = 0;
    #pragma unroll
    for (int k = 0; k < 16; ++k) {
        float4 f = gp4[k*32 + lane];    // points g0 = 2*(k*32+lane), g0+1
        int g0 = 2*(k*32 + lane);
        float dx = __fsub_rn(px, f.x), dy = __fsub_rn(py, f.y);
        float d2 = __fadd_rn(__fmul_rn(dx,dx), __fmul_rn(dy,dy));
        if (d2 < bestd2) { bestd2 = d2; bestg = g0; }       // SEL-predicated
        dx = __fsub_rn(px, f.z); dy = __fsub_rn(py, f.w);
        d2 = __fadd_rn(__fmul_rn(dx,dx), __fmul_rn(dy,dy));
        if (d2 < bestd2) { bestd2 = d2; bestg = g0 + 1; }
    }
    u64 key = ((u64)__float_as_uint(bestd2) << 32) | (unsigned)bestg;
    #pragma unroll
    for (int o = 16; o; o >>= 1) {
        u64 other = __shfl_xor_sync(0xffffffffu, key, o);
        if (other < key) key = other;   // tie -> smaller g (low bits)
    }
    __syncthreads();                    // s_cd/s_sem/s_nm initialized

    if (lane == 0) {
        int gb  = (int)(key & 0xffffffffULL);
        float d = sqrtf(__uint_as_float((unsigned)(key >> 32)));  // one sqrt
        g_nearest[pred] = gb;
        atomicMax(&s_nm, gb);
        atomicAdd(&s_cd, d);
        u64 pk = ((u64)__float_as_uint(d) << 32) | (unsigned)pi;
        atomicMax(&g_bestg[b*GG + gb], ~pk);          // min(key) == max(~key)
        int cls = gt_type[b*GG + gb];
        s_cls[wid] = cls;
        atomicAdd(&s_sem, semantics[(size_t)b*CC*NN + (size_t)cls*NN + pi]);
    }
    __syncthreads();

    if (tid < 24) {                     // sg: 3 classes x 8 consecutive preds
        int c = tid >> 3, k = tid & 7;
        int p0 = (blockIdx.x & 255)*8;  // pred-in-batch base for this block
        sg_out[(size_t)b*CC*NN + (size_t)c*NN + p0 + k] = (s_cls[k]==c) ? 1.f : 0.f;
    }
    if (tid == 0) {
        atomicAdd(&g_cd[b], s_cd);
        atomicAdd(&g_sem[b], s_sem);
        atomicMax(&g_nmax[b], s_nm);
    }
}

// ===== K2a: walk once per g. 16 blocks (4/batch), batch staged in smem =====
__global__ void __launch_bounds__(256) k2a_walk(const int* __restrict__ gt_ins)
{
    __shared__ int s_ins[GG];
    __shared__ int s_bp[GG];            // best pred + 1, 0 = none

    int b   = blockIdx.x >> 2;
    int g0  = (blockIdx.x & 3) * 256;
    int tid = threadIdx.x;

    for (int g = tid; g < GG; g += 256) {
        s_ins[g] = gt_ins[b*GG + g];
        u64 v = g_bestg[b*GG + g];
        s_bp[g] = v ? (int)((~v) & 0xffffffffULL) + 1 : 0;
    }
    __syncthreads();
    int nmaxb = g_nmax[b];

    int g = g0 + tid;
    int idx = g, steps = 0, res = -1;
    while (true) {                      // literal jax while_loop transcription
        bool is_end = (idx >= nmaxb);
        int  gnr    = is_end ? -1 : (idx + 1);
        int  gn     = gnr & (GG-1);
        int  bp     = s_bp[gn];
        bool ex     = (!is_end) && (bp != 0);
        bool same   = (s_ins[idx & (GG-1)] == s_ins[gn]);
        bool matched= ex && same;
        res  = matched ? bp - 1 : -1;
        bool stop = matched || (!same) || (steps >= GG + 2);
        idx = gnr; steps++;
        if (stop) break;
    }
    g_nextg[b*GG + g] = res;
}

// ===== K2b: per-pred counts + keep (global atomics); clean bestg/nmax ======
__global__ void __launch_bounds__(256) k2b_count(const float* __restrict__ positions)
{
    int t = blockIdx.x*blockDim.x + threadIdx.x;     // BB*NN threads
    int b = t >> 11, i = t & (NN-1);
    int res = g_nextg[b*GG + g_nearest[t]];
    g_next[t] = res;
    if (res >= 0) {
        atomicAdd(&g_cnt[b*NN + res], 1);
        float2 pi = ((const float2*)positions)[t];
        float2 pj = ((const float2*)positions)[b*NN + res];
        float d = pdist(posx_of(pi.x), posy_of(pi.y), posx_of(pj.x), posy_of(pj.y));
        u64 pk = ((u64)__float_as_uint(d) << 32) | (unsigned)i;
        atomicMax(&g_keep[b*NN + res], ~pk);
    }
    if (t < BB*GG) g_bestg[t] = 0ULL;                // self-clean (K2a done)
    if (t < BB)    g_nmax[t]  = 0;
}

// ===== K3: targets + scatter ones + loss gathers + finalize ================
__global__ void __launch_bounds__(256) k3_scatter(const float* __restrict__ matches,
                                                  float* __restrict__ out)
{
    int t = blockIdx.x*blockDim.x + threadIdx.x;     // BB*NN threads
    int b = t >> 11, i = t & (NN-1);
    int res = g_next[t];
    int tf;
    if (res >= 0) {
        int cnt = g_cnt[b*NN + res];
        int keeprow = (int)((~g_keep[b*NN + res]) & 0xffffffffULL);
        tf = (cnt <= 1 || keeprow == i) ? res : (MM-1);
    } else tf = MM-1;

    int cj = g_cnt[t];
    int tb = (cj == 0) ? (MM-1) : (int)((~g_keep[t]) & 0xffffffffULL);

    size_t rowbase = (size_t)b*MMQ + (size_t)i*MM;
    out[3 + rowbase + tf] = 1.0f;                    // row i's single 1
    if (tb == MM-1)                                  // col i empty -> last row
        out[3 + (size_t)b*MMQ + (size_t)NN*MM + i] = 1.0f;

    float fv = matches[rowbase + tf];                // match[i, tgt_f[i]]
    float bv = matches[rowbase + tb];                // match[i, tgt_b[i]]
    #pragma unroll
    for (int o = 16; o; o >>= 1) {
        fv += __shfl_xor_sync(0xffffffffu, fv, o);
        bv += __shfl_xor_sync(0xffffffffu, bv, o);
    }
    if ((threadIdx.x & 31) == 0) {                   // b warp-uniform
        atomicAdd(&g_mf[b], fv);
        atomicAdd(&g_mb[b], bv);
    }
    __syncthreads();

    if (threadIdx.x == 0) {
        __threadfence();
        if (atomicAdd(&g_ticket, 1u) == gridDim.x - 1) {   // last block
            float cm = 0.f, ml = 0.f, sl = 0.f;
            const float invN = 1.0f / NN;
            #pragma unroll
            for (int bb = 0; bb < BB; ++bb) {
                cm += g_cd[bb] * invN;
                sl += -g_sem[bb] * invN;
                float lf = -g_mf[bb] * invN;
                float lb = -g_mb[bb] * invN;
                ml += 0.5f * (lf + lb);
                g_cd[bb]=0.f; g_sem[bb]=0.f; g_mf[bb]=0.f; g_mb[bb]=0.f;
            }
            const float invB = 1.0f / BB;
            out[0] = cm * invB;
            out[1] = ml * invB;
            out[2] = sl * invB;
            g_ticket = 0u;                           // self-clean
        }
    }
}

extern "C" void kernel_launch(void* const* d_in, const int* in_sizes, int n_in,
                              void* d_out, int out_size)
{
    const float* matches   = (const float*)d_in[0];
    const float* positions = (const float*)d_in[1];
    const float* semantics = (const float*)d_in[2];
    /* d_in[3] masks: unused by reference */
    const float* gt_pts    = (const float*)d_in[4];
    const int*   gt_ins    = (const int*)d_in[5];
    const int*   gt_type   = (const int*)d_in[6];

    float* out = (float*)d_out;
    float* sg  = out + 3 + (size_t)BB*MMQ;

    k1_zero_nearest<<<NBLK + ZBLK, 256>>>(positions, gt_pts, gt_type,
                                          semantics, out, sg);
    k2a_walk<<<BB*4, 256>>>(gt_ins);
    k2b_count<<<BB*NN/256, 256>>>(positions);
    k3_scatter<<<BB*NN/256, 256>>>(matches, out);
}

// round 12
// speedup vs baseline: 1.1861x; 1.0889x over previous
#include <cuda_runtime.h>

#define BB 4
#define NN 2048
#define MM 2049
#define GG 1024
#define CC 3
#define MMQ (MM*MM)                 // 4198401

typedef unsigned long long u64;

// ---------------- scratch (device globals, zero-initialized at load) --------
// Cleaning schedule (race-free across graph replays):
//   g_bestg/g_nmax : written K1 (atomicMax), read K2a, cleaned K2b
//   g_cnt/g_keep   : written K2b, read K3 (cross-thread), cleaned by NEXT
//                    replay's K1 zero-blocks (run before K2b)
//   g_cd/g_sem/g_mf/g_mb : atomic-acc, cleaned in K3 finalize
//   g_nearest/g_nextg/g_next : fully overwritten every replay
__device__ u64   g_bestg[BB*GG];    // ~((distbits<<32)|pred); 0 = unassigned
__device__ int   g_nmax[BB];
__device__ int   g_nearest[BB*NN];
__device__ int   g_nextg[BB*GG];
__device__ int   g_next[BB*NN];
__device__ int   g_cnt[BB*NN];
__device__ u64   g_keep[BB*NN];     // ~((distbits<<32)|row); 0 = empty
__device__ float g_cd[BB], g_sem[BB];
__device__ float g_mf[BB], g_mb[BB];
__device__ unsigned g_ticket;

// pos = position * 0.15 + bias, NO fma contraction (match XLA's separate ops)
__device__ __forceinline__ float posx_of(float p){ return __fadd_rn(__fmul_rn(p,0.15f), -29.925f); }
__device__ __forceinline__ float posy_of(float p){ return __fadd_rn(__fmul_rn(p,0.15f), -14.925f); }

__device__ __forceinline__ float pdist(float ax,float ay,float bx,float by){
    float dx = __fsub_rn(ax,bx), dy = __fsub_rn(ay,by);
    float d2 = __fadd_rn(__fmul_rn(dx,dx), __fmul_rn(dy,dy));
    return sqrtf(d2);
}

// ===== K1: [blocks 0..511] nearest-gt (warp = 2 preds)  ++
//           [blocks 512..4612] zero-fill A region + clean cnt/keep ==========
#define NBLK 512                        // BB*NN/16 nearest blocks
#define ZVEC 4198401                    // float4 count of zero region
#define ZBLK 4101                       // ceil(ZVEC/1024)

__global__ void __launch_bounds__(256) k1_zero_nearest(
                           const float* __restrict__ positions,
                           const float* __restrict__ gt_pts,
                           const int*   __restrict__ gt_type,
                           const float* __restrict__ semantics,
                           float* __restrict__ out,
                           float* __restrict__ sg_out)
{
    if (blockIdx.x >= NBLK) {           // ---------- zero blocks ------------
        unsigned zb = blockIdx.x - NBLK;
        float4* vout = (float4*)out;
        #pragma unroll
        for (int k = 0; k < 4; ++k) {
            unsigned v = zb*1024u + k*256u + threadIdx.x;
            if (v < ZVEC) vout[v] = make_float4(0.f,0.f,0.f,0.f);
        }
        if (zb < 32) {                  // clean cnt/keep for this replay's K2b
            int idx = zb*256 + threadIdx.x;      // covers BB*NN = 8192
            g_cnt[idx] = 0;
            g_keep[idx] = 0ULL;
        }
        if (zb == 0 && threadIdx.x == 0) {
            out[16793604] = 0.f; out[16793605] = 0.f; out[16793606] = 0.f;
        }
        return;
    }

    // -------- nearest blocks: 8 warps x 2 preds = 16 preds per block -------
    __shared__ float s_cd, s_sem;
    __shared__ int   s_nm;
    __shared__ int   s_cls[16];

    int tid   = threadIdx.x;
    int wid   = tid >> 5;
    int lane  = tid & 31;
    int predA = blockIdx.x*16 + wid*2;  // global pred ids predA, predA+1
    int b     = predA >> 11;            // 16 preds never straddle a batch

    if (tid == 0) { s_cd = 0.f; s_sem = 0.f; s_nm = 0; }

    float2 prA = ((const float2*)positions)[predA];
    float2 prB = ((const float2*)positions)[predA + 1];
    float pxA = posx_of(prA.x), pyA = posy_of(prA.y);
    float pxB = posx_of(prB.x), pyB = posy_of(prB.y);

    const float4* gp4 = (const float4*)(gt_pts + (size_t)b*GG*2);  // 512 float4

    // Branchless argmin over d2 for TWO preds per gt load. sqrt monotone =>
    // argmin(d2), strict < in ascending-g order == first-index argmin(sqrt);
    // one sqrt after the reduction recovers the exact min distance.
    float bd2A = 3.4e38f, bd2B = 3.4e38f; int bgA = 0, bgB = 0;
    #pragma unroll
    for (int k = 0; k < 16; ++k) {
        float4 f = gp4[k*32 + lane];    // candidates g0 = 2*(k*32+lane), g0+1
        int g0 = 2*(k*32 + lane);
        float dx, dy, d2;
        dx = __fsub_rn(pxA, f.x); dy = __fsub_rn(pyA, f.y);
        d2 = __fadd_rn(__fmul_rn(dx,dx), __fmul_rn(dy,dy));
        if (d2 < bd2A) { bd2A = d2; bgA = g0; }
        dx = __fsub_rn(pxA, f.z); dy = __fsub_rn(pyA, f.w);
        d2 = __fadd_rn(__fmul_rn(dx,dx), __fmul_rn(dy,dy));
        if (d2 < bd2A) { bd2A = d2; bgA = g0 + 1; }
        dx = __fsub_rn(pxB, f.x); dy = __fsub_rn(pyB, f.y);
        d2 = __fadd_rn(__fmul_rn(dx,dx), __fmul_rn(dy,dy));
        if (d2 < bd2B) { bd2B = d2; bgB = g0; }
        dx = __fsub_rn(pxB, f.z); dy = __fsub_rn(pyB, f.w);
        d2 = __fadd_rn(__fmul_rn(dx,dx), __fmul_rn(dy,dy));
        if (d2 < bd2B) { bd2B = d2; bgB = g0 + 1; }
    }
    u64 keyA = ((u64)__float_as_uint(bd2A) << 32) | (unsigned)bgA;
    u64 keyB = ((u64)__float_as_uint(bd2B) << 32) | (unsigned)bgB;
    #pragma unroll
    for (int o = 16; o; o >>= 1) {      // two independent reductions (ILP)
        u64 oa = __shfl_xor_sync(0xffffffffu, keyA, o);
        u64 ob = __shfl_xor_sync(0xffffffffu, keyB, o);
        if (oa < keyA) keyA = oa;       // tie -> smaller g (low bits)
        if (ob < keyB) keyB = ob;
    }
    __syncthreads();                    // s_cd/s_sem/s_nm initialized

    if (lane < 2) {                     // lane0 commits predA, lane1 predB
        u64 key  = (lane == 0) ? keyA : keyB;
        int pred = predA + lane;
        int pi   = pred & (NN-1);
        int gb  = (int)(key & 0xffffffffULL);
        float d = sqrtf(__uint_as_float((unsigned)(key >> 32)));  // one sqrt
        g_nearest[pred] = gb;
        atomicMax(&s_nm, gb);
        atomicAdd(&s_cd, d);
        u64 pk = ((u64)__float_as_uint(d) << 32) | (unsigned)pi;
        atomicMax(&g_bestg[b*GG + gb], ~pk);          // min(key) == max(~key)
        int cls = gt_type[b*GG + gb];
        s_cls[wid*2 + lane] = cls;
        atomicAdd(&s_sem, semantics[(size_t)b*CC*NN + (size_t)cls*NN + pi]);
    }
    __syncthreads();

    if (tid < 48) {                     // sg: 3 classes x 16 consecutive preds
        int c = tid >> 4, k = tid & 15;
        int p0 = (blockIdx.x & 127)*16; // pred-in-batch base for this block
        sg_out[(size_t)b*CC*NN + (size_t)c*NN + p0 + k] = (s_cls[k]==c) ? 1.f : 0.f;
    }
    if (tid == 0) {
        atomicAdd(&g_cd[b], s_cd);
        atomicAdd(&g_sem[b], s_sem);
        atomicMax(&g_nmax[b], s_nm);
    }
}

// ===== K2a: walk once per g. 16 blocks (4/batch), batch staged in smem =====
__global__ void __launch_bounds__(256) k2a_walk(const int* __restrict__ gt_ins)
{
    __shared__ int s_ins[GG];
    __shared__ int s_bp[GG];            // best pred + 1, 0 = none

    int b   = blockIdx.x >> 2;
    int g0  = (blockIdx.x & 3) * 256;
    int tid = threadIdx.x;

    for (int g = tid; g < GG; g += 256) {
        s_ins[g] = gt_ins[b*GG + g];
        u64 v = g_bestg[b*GG + g];
        s_bp[g] = v ? (int)((~v) & 0xffffffffULL) + 1 : 0;
    }
    __syncthreads();
    int nmaxb = g_nmax[b];

    int g = g0 + tid;
    int idx = g, steps = 0, res = -1;
    while (true) {                      // literal jax while_loop transcription
        bool is_end = (idx >= nmaxb);
        int  gnr    = is_end ? -1 : (idx + 1);
        int  gn     = gnr & (GG-1);
        int  bp     = s_bp[gn];
        bool ex     = (!is_end) && (bp != 0);
        bool same   = (s_ins[idx & (GG-1)] == s_ins[gn]);
        bool matched= ex && same;
        res  = matched ? bp - 1 : -1;
        bool stop = matched || (!same) || (steps >= GG + 2);
        idx = gnr; steps++;
        if (stop) break;
    }
    g_nextg[b*GG + g] = res;
}

// ===== K2b: per-pred counts + keep (global atomics); clean bestg/nmax ======
__global__ void __launch_bounds__(256) k2b_count(const float* __restrict__ positions)
{
    int t = blockIdx.x*blockDim.x + threadIdx.x;     // BB*NN threads
    int b = t >> 11, i = t & (NN-1);
    int res = g_nextg[b*GG + g_nearest[t]];
    g_next[t] = res;
    if (res >= 0) {
        atomicAdd(&g_cnt[b*NN + res], 1);
        float2 pi = ((const float2*)positions)[t];
        float2 pj = ((const float2*)positions)[b*NN + res];
        float d = pdist(posx_of(pi.x), posy_of(pi.y), posx_of(pj.x), posy_of(pj.y));
        u64 pk = ((u64)__float_as_uint(d) << 32) | (unsigned)i;
        atomicMax(&g_keep[b*NN + res], ~pk);
    }
    if (t < BB*GG) g_bestg[t] = 0ULL;                // self-clean (K2a done)
    if (t < BB)    g_nmax[t]  = 0;
}

// ===== K3: rows + cols in parallel halves; scatter + losses + finalize =====
__global__ void __launch_bounds__(256) k3_scatter(const float* __restrict__ matches,
                                                  float* __restrict__ out)
{
    int t = blockIdx.x*blockDim.x + threadIdx.x;     // 2*BB*NN threads
    float v;
    float* acc;
    int b;
    if (t < BB*NN) {                    // ---------------- row side ---------
        b = t >> 11; int i = t & (NN-1);
        int res = g_next[t];
        int tf;
        if (res >= 0) {
            int cnt = g_cnt[b*NN + res];
            int keeprow = (int)((~g_keep[b*NN + res]) & 0xffffffffULL);
            tf = (cnt <= 1 || keeprow == i) ? res : (MM-1);
        } else tf = MM-1;
        size_t rowbase = (size_t)b*MMQ + (size_t)i*MM;
        out[3 + rowbase + tf] = 1.0f;   // row i's single 1
        v = matches[rowbase + tf];      // match[i, tgt_f[i]]
        acc = g_mf;
    } else {                            // ---------------- col side ---------
        int u = t - BB*NN; b = u >> 11; int j = u & (NN-1);
        int cj = g_cnt[u];
        int tb;
        if (cj == 0) {
            tb = MM-1;
            out[3 + (size_t)b*MMQ + (size_t)NN*MM + j] = 1.0f;  // last row 1
        } else {
            tb = (int)((~g_keep[u]) & 0xffffffffULL);
        }
        v = matches[(size_t)b*MMQ + (size_t)j*MM + tb];  // match[j, tgt_b[j]]
        acc = g_mb;
    }
    #pragma unroll
    for (int o = 16; o; o >>= 1) v += __shfl_xor_sync(0xffffffffu, v, o);
    if ((threadIdx.x & 31) == 0) atomicAdd(&acc[b], v);  // b warp-uniform
    __syncthreads();

    if (threadIdx.x == 0) {
        __threadfence();
        if (atomicAdd(&g_ticket, 1u) == gridDim.x - 1) {   // last block
            float cm = 0.f, ml = 0.f, sl = 0.f;
            const float invN = 1.0f / NN;
            #pragma unroll
            for (int bb = 0; bb < BB; ++bb) {
                cm += g_cd[bb] * invN;
                sl += -g_sem[bb] * invN;
                float lf = -g_mf[bb] * invN;
                float lb = -g_mb[bb] * invN;
                ml += 0.5f * (lf + lb);
                g_cd[bb]=0.f; g_sem[bb]=0.f; g_mf[bb]=0.f; g_mb[bb]=0.f;
            }
            const float invB = 1.0f / BB;
            out[0] = cm * invB;
            out[1] = ml * invB;
            out[2] = sl * invB;
            g_ticket = 0u;              // self-clean
        }
    }
}

extern "C" void kernel_launch(void* const* d_in, const int* in_sizes, int n_in,
                              void* d_out, int out_size)
{
    const float* matches   = (const float*)d_in[0];
    const float* positions = (const float*)d_in[1];
    const float* semantics = (const float*)d_in[2];
    /* d_in[3] masks: unused by reference */
    const float* gt_pts    = (const float*)d_in[4];
    const int*   gt_ins    = (const int*)d_in[5];
    const int*   gt_type   = (const int*)d_in[6];

    float* out = (float*)d_out;
    float* sg  = out + 3 + (size_t)BB*MMQ;

    k1_zero_nearest<<<NBLK + ZBLK, 256>>>(positions, gt_pts, gt_type,
                                          semantics, out, sg);
    k2a_walk<<<BB*4, 256>>>(gt_ins);
    k2b_count<<<BB*NN/256, 256>>>(positions);
    k3_scatter<<<2*BB*NN/256, 256>>>(matches, out);
}